// round 7
// baseline (speedup 1.0000x reference)
#include <cuda_runtime.h>
#include <cstdint>

#define N_NODES 100000
#define N_EDGES 1250000
#define D_IN    64
#define OUT_COLS 300
#define WC_COLS 320     // padded output columns
#define WC_ROWS 192     // 3 x 64 (T0, T1, T2p)
#define SCAN_BS 1024
#define SCAN_NB ((N_NODES + SCAN_BS - 1) / SCAN_BS)   // 98

// ---------------- scratch (device globals: allocation-free) ----------------
__device__ __align__(16) float  g_dis[N_NODES];          // deg, then rsqrt(deg)
__device__ __align__(16) int    g_cnt[N_NODES];          // in-degree histogram
__device__ __align__(16) int    g_scan[N_NODES];         // block-inclusive scan
__device__ __align__(16) int    g_bsum[SCAN_NB];         // per-block sums
__device__ __align__(16) int    g_boff[SCAN_NB];         // exclusive block offsets
__device__ __align__(16) int    g_off[N_NODES + 1];      // CSR offsets
__device__ __align__(16) int    g_cur[N_NODES];          // fill cursors
__device__ __align__(16) float2 g_pack[N_EDGES];         // (src bitcast, w_hat)
__device__ __align__(16) float  g_T1[N_NODES * D_IN];    // prop(x)
__device__ __align__(16) float  g_T2[N_NODES * D_IN];    // prop(T1)
__device__ __align__(16) float  g_Wc[WC_ROWS * WC_COLS]; // combined weight matrix
__device__ __align__(16) float  g_bias[WC_COLS];         // concat bias (padded)
__device__ int g_is64;                                   // edge_index dtype flag

// ---------------- edge index access (dtype-adaptive) ----------------
// If the buffer is int64 (little-endian, values < 2^31), the int32 view has
// zero in every odd word. If int32, odd words are random node ids.
__global__ void detect_dtype_kernel(const int* __restrict__ ei32) {
    __shared__ int nz;
    if (threadIdx.x == 0) nz = 0;
    __syncthreads();
    int w = 2 * threadIdx.x + 1;   // odd words of first 512 ints
    if (ei32[w] != 0) atomicAdd(&nz, 1);
    __syncthreads();
    if (threadIdx.x == 0) g_is64 = (nz == 0) ? 1 : 0;
}

__device__ __forceinline__ void load_edge(const void* ei, int e, unsigned& r, unsigned& c) {
    if (g_is64) {
        const long long* p = (const long long*)ei;
        r = (unsigned)(int)p[e];
        c = (unsigned)(int)p[N_EDGES + e];
    } else {
        const int* p = (const int*)ei;
        r = (unsigned)p[e];
        c = (unsigned)p[N_EDGES + e];
    }
}

// ---------------- kernels ----------------

__global__ void zero_kernel() {
    int i = blockIdx.x * blockDim.x + threadIdx.x;
    if (i < N_NODES) { g_dis[i] = 0.f; g_cnt[i] = 0; }
}

// degree (by row, scalar f32 atomic) + in-degree histogram (by col, s32 atomic)
__global__ void deg_hist_kernel(const void* __restrict__ ei, const float* __restrict__ ew) {
    int e = blockIdx.x * blockDim.x + threadIdx.x;
    if (e < N_EDGES) {
        unsigned r, c;
        load_edge(ei, e, r, c);
        if (r < N_NODES) atomicAdd(&g_dis[r], ew[e]);
        if (c < N_NODES) atomicAdd(&g_cnt[c], 1);
    }
}

__global__ void dis_kernel() {
    int i = blockIdx.x * blockDim.x + threadIdx.x;
    if (i < N_NODES) {
        float d = g_dis[i];
        g_dis[i] = (d > 0.f) ? rsqrtf(d) : 0.f;
    }
}

// ---- 3-kernel exclusive scan of g_cnt -> g_off ----
__global__ void scan1_kernel() {
    __shared__ int s[SCAN_BS];
    int t = threadIdx.x;
    int i = blockIdx.x * SCAN_BS + t;
    int v = (i < N_NODES) ? g_cnt[i] : 0;
    s[t] = v;
    __syncthreads();
    for (int d = 1; d < SCAN_BS; d <<= 1) {
        int add = (t >= d) ? s[t - d] : 0;
        __syncthreads();
        s[t] += add;
        __syncthreads();
    }
    if (i < N_NODES) g_scan[i] = s[t];
    if (t == SCAN_BS - 1) g_bsum[blockIdx.x] = s[t];
}

__global__ void scan2_kernel() {
    __shared__ int s[128];
    int t = threadIdx.x;
    int v = (t < SCAN_NB) ? g_bsum[t] : 0;
    s[t] = v;
    __syncthreads();
    for (int d = 1; d < 128; d <<= 1) {
        int add = (t >= d) ? s[t - d] : 0;
        __syncthreads();
        s[t] += add;
        __syncthreads();
    }
    if (t < SCAN_NB) g_boff[t] = s[t] - v;   // exclusive
}

__global__ void finalize_off_kernel() {
    int i = blockIdx.x * blockDim.x + threadIdx.x;
    if (i < N_NODES) {
        int incl = g_scan[i] + g_boff[i / SCAN_BS];
        int excl = incl - g_cnt[i];
        g_off[i] = excl;
        g_cur[i] = excl;
        if (i == N_NODES - 1) g_off[N_NODES] = incl;
    }
}

// fill CSR: pack (src_row, w_hat) per edge, bucketed by destination col
__global__ void fill_kernel(const void* __restrict__ ei, const float* __restrict__ ew) {
    int e = blockIdx.x * blockDim.x + threadIdx.x;
    if (e < N_EDGES) {
        unsigned r, c;
        load_edge(ei, e, r, c);
        if (r >= N_NODES || c >= N_NODES) return;
        float w = -g_dis[r] * ew[e] * g_dis[c];
        unsigned slot = (unsigned)atomicAdd(&g_cur[c], 1);
        if (slot >= N_EDGES) slot = N_EDGES - 1;
        g_pack[slot] = make_float2(__int_as_float((int)r), w);
    }
}

// gather prop: dst[c] = sum_{e in CSR[c]} w_e * src[r_e].  One warp per node,
// each lane owns one float2 (2 of 64 features). No atomics, no zero-init.
// phase 0: src = x (arg), dst = g_T1 ; phase 1: src = g_T1, dst = g_T2.
__global__ void __launch_bounds__(256)
prop_kernel(const float* __restrict__ x, int phase) {
    int gt = blockIdx.x * blockDim.x + threadIdx.x;
    int node = gt >> 5;
    int lane = gt & 31;
    if (node >= N_NODES) return;
    const float* src = (phase == 0) ? x : g_T1;
    float*       dst = (phase == 0) ? g_T1 : g_T2;
    int beg = g_off[node];
    int end = g_off[node + 1];
    if (beg < 0) beg = 0;
    if (end > N_EDGES) end = N_EDGES;
    const float2* s2 = reinterpret_cast<const float2*>(src);
    float ax = 0.f, ay = 0.f;
    int j = beg;
    for (; j + 2 <= end; j += 2) {
        float2 p0 = g_pack[j];
        float2 p1 = g_pack[j + 1];
        unsigned r0 = min((unsigned)__float_as_int(p0.x), N_NODES - 1u);
        unsigned r1 = min((unsigned)__float_as_int(p1.x), N_NODES - 1u);
        float2 v0 = s2[r0 * 32 + lane];
        float2 v1 = s2[r1 * 32 + lane];
        ax += p0.y * v0.x;  ay += p0.y * v0.y;
        ax += p1.y * v1.x;  ay += p1.y * v1.y;
    }
    if (j < end) {
        float2 p0 = g_pack[j];
        unsigned r0 = min((unsigned)__float_as_int(p0.x), N_NODES - 1u);
        float2 v0 = s2[r0 * 32 + lane];
        ax += p0.y * v0.x;  ay += p0.y * v0.y;
    }
    reinterpret_cast<float2*>(dst)[node * 32 + lane] = make_float2(ax, ay);
}

// Build combined weight matrix Wc[192][320] and bias[320]:
//  rows 0-63   (x):    [ W10 | W20 | W30 - W32 | 0 ]
//  rows 64-127 (T1):   [  0  | W21 |    W31    | 0 ]
//  rows 128-191(T2p):  [  0  |  0  |  2*W32    | 0 ]
__global__ void prep_weights_kernel(
    const float* __restrict__ W10, const float* __restrict__ b1,
    const float* __restrict__ W20, const float* __restrict__ W21, const float* __restrict__ b2,
    const float* __restrict__ W30, const float* __restrict__ W31, const float* __restrict__ W32,
    const float* __restrict__ b3)
{
    int i = blockIdx.x * blockDim.x + threadIdx.x;
    if (i >= WC_ROWS * WC_COLS) return;
    int k = i / WC_COLS;
    int c = i % WC_COLS;
    float v = 0.f;
    if (k < 64) {
        if (c < 100)       v = W10[k * 100 + c];
        else if (c < 200)  v = W20[k * 100 + (c - 100)];
        else if (c < 300)  v = W30[k * 100 + (c - 200)] - W32[k * 100 + (c - 200)];
    } else if (k < 128) {
        int kk = k - 64;
        if (c >= 100 && c < 200)      v = W21[kk * 100 + (c - 100)];
        else if (c >= 200 && c < 300) v = W31[kk * 100 + (c - 200)];
    } else {
        int kk = k - 128;
        if (c >= 200 && c < 300) v = 2.f * W32[kk * 100 + (c - 200)];
    }
    g_Wc[i] = v;
    if (i < WC_COLS) {
        float bv = 0.f;
        if (i < 100)      bv = b1[i];
        else if (i < 200) bv = b2[i - 100];
        else if (i < 300) bv = b3[i - 200];
        g_bias[i] = bv;
    }
}

// GEMM: out[100000, 300] = [x | T1 | T2p] @ Wc + bias
// Block: 64 nodes x 64 cols, 256 threads, 4x4 outputs/thread.
// grid.y = column tile (5 tiles of 64); K chunks per tile: {1,2,2,3,3}.
#define GU_STRIDE 68
#define GW_STRIDE 68

__global__ void __launch_bounds__(256)
gemm_kernel(const float* __restrict__ x, float* __restrict__ out)
{
    __shared__ float Usm[64 * GU_STRIDE];
    __shared__ float Wsm[64 * GW_STRIDE];

    const int tid = threadIdx.x;
    const int tx = tid & 15;
    const int ty = tid >> 4;
    const int nodeBase = blockIdx.x * 64;
    const int ct = blockIdx.y;
    const int colBase = ct * 64;
    const int nchunks = (ct == 0) ? 1 : (ct < 3) ? 2 : 3;

    float acc[4][4];
    for (int j = 0; j < 4; j++)
        for (int c = 0; c < 4; c++) acc[j][c] = 0.f;

    for (int kc = 0; kc < nchunks; kc++) {
        const float4* src = (kc == 0) ? reinterpret_cast<const float4*>(x)
                          : (kc == 1) ? reinterpret_cast<const float4*>(g_T1)
                                      : reinterpret_cast<const float4*>(g_T2);
        for (int i = 0; i < 4; i++) {
            int idx = tid + i * 256;
            int node = idx >> 4;
            int k4 = idx & 15;
            int gn = nodeBase + node;
            float4 v = make_float4(0.f, 0.f, 0.f, 0.f);
            if (gn < N_NODES) v = src[gn * 16 + k4];
            *reinterpret_cast<float4*>(&Usm[node * GU_STRIDE + k4 * 4]) = v;
        }
        for (int i = 0; i < 4; i++) {
            int idx = tid + i * 256;
            int k = idx >> 4;
            int c4 = idx & 15;
            float4 wv = *reinterpret_cast<const float4*>(
                &g_Wc[(kc * 64 + k) * WC_COLS + colBase + c4 * 4]);
            *reinterpret_cast<float4*>(&Wsm[k * GW_STRIDE + c4 * 4]) = wv;
        }
        __syncthreads();

#pragma unroll 4
        for (int k = 0; k < 64; k++) {
            float4 w = *reinterpret_cast<const float4*>(&Wsm[k * GW_STRIDE + tx * 4]);
            float u0 = Usm[(ty * 4 + 0) * GU_STRIDE + k];
            float u1 = Usm[(ty * 4 + 1) * GU_STRIDE + k];
            float u2 = Usm[(ty * 4 + 2) * GU_STRIDE + k];
            float u3 = Usm[(ty * 4 + 3) * GU_STRIDE + k];
            acc[0][0] += u0 * w.x; acc[0][1] += u0 * w.y; acc[0][2] += u0 * w.z; acc[0][3] += u0 * w.w;
            acc[1][0] += u1 * w.x; acc[1][1] += u1 * w.y; acc[1][2] += u1 * w.z; acc[1][3] += u1 * w.w;
            acc[2][0] += u2 * w.x; acc[2][1] += u2 * w.y; acc[2][2] += u2 * w.z; acc[2][3] += u2 * w.w;
            acc[3][0] += u3 * w.x; acc[3][1] += u3 * w.y; acc[3][2] += u3 * w.z; acc[3][3] += u3 * w.w;
        }
        __syncthreads();
    }

    int col = colBase + tx * 4;
    if (col < OUT_COLS) {
        float4 bv = *reinterpret_cast<const float4*>(&g_bias[col]);
        for (int j = 0; j < 4; j++) {
            int node = nodeBase + ty * 4 + j;
            if (node >= N_NODES) continue;
            float4 o = make_float4(acc[j][0] + bv.x, acc[j][1] + bv.y,
                                   acc[j][2] + bv.z, acc[j][3] + bv.w);
            *reinterpret_cast<float4*>(&out[(long long)node * OUT_COLS + col]) = o;
        }
    }
}

// ---------------- launch ----------------
extern "C" void kernel_launch(void* const* d_in, const int* in_sizes, int n_in,
                              void* d_out, int out_size)
{
    // Resolve inputs BY SIZE SIGNATURE (robust to ordering among same-sized buffers):
    const float* x = nullptr;
    const void*  ei = nullptr;
    const float* ew = nullptr;
    const float* Ws[6] = {};
    const float* Bs[3] = {};
    int nw = 0, nb = 0;
    for (int i = 0; i < n_in; i++) {
        int s = in_sizes[i];
        if (s == N_NODES * D_IN)      x = (const float*)d_in[i];
        else if (s == 2 * N_EDGES)    ei = d_in[i];
        else if (s == N_EDGES)        ew = (const float*)d_in[i];
        else if (s == D_IN * 100)     { if (nw < 6) Ws[nw++] = (const float*)d_in[i]; }
        else if (s == 100)            { if (nb < 3) Bs[nb++] = (const float*)d_in[i]; }
    }
    if (!x)  x  = (const float*)d_in[0];
    if (!ei) ei = d_in[1];
    if (!ew) ew = (const float*)d_in[2];
    if (nw < 6) {
        Ws[0] = (const float*)d_in[3];  Ws[1] = (const float*)d_in[5];
        Ws[2] = (const float*)d_in[6];  Ws[3] = (const float*)d_in[8];
        Ws[4] = (const float*)d_in[9];  Ws[5] = (const float*)d_in[10];
    }
    if (nb < 3) {
        Bs[0] = (const float*)d_in[4];  Bs[1] = (const float*)d_in[7];
        Bs[2] = (const float*)d_in[11];
    }
    float* out = (float*)d_out;

    const int B = 256;
    const int nodeGrid = (N_NODES + B - 1) / B;
    const int edgeGrid = (N_EDGES + B - 1) / B;

    detect_dtype_kernel<<<1, 256>>>((const int*)ei);
    zero_kernel<<<nodeGrid, B>>>();
    deg_hist_kernel<<<edgeGrid, B>>>(ei, ew);
    dis_kernel<<<nodeGrid, B>>>();
    scan1_kernel<<<SCAN_NB, SCAN_BS>>>();
    scan2_kernel<<<1, 128>>>();
    finalize_off_kernel<<<nodeGrid, B>>>();
    fill_kernel<<<edgeGrid, B>>>(ei, ew);

    {   // T1 = P x ; T2p = P T1
        long long items = (long long)N_NODES * 32;
        int grid = (int)((items + B - 1) / B);
        prop_kernel<<<grid, B>>>(x, 0);
        prop_kernel<<<grid, B>>>(x, 1);
    }

    prep_weights_kernel<<<(WC_ROWS * WC_COLS + B - 1) / B, B>>>(
        Ws[0], Bs[0], Ws[1], Ws[2], Bs[1], Ws[3], Ws[4], Ws[5], Bs[2]);

    {
        dim3 grid((N_NODES + 63) / 64, 5);
        gemm_kernel<<<grid, 256>>>(x, out);
    }
}